// round 3
// baseline (speedup 1.0000x reference)
#include <cuda_runtime.h>

#define GRID_G   152
#define GG       (152 * 152)          // 23104
#define NA       3
#define NCH      10                   // 7 + 3 classes
#define NB       64
#define NPOS     (NB * NA * GG)       // 4,435,968 = 8664 * 512 exactly
#define STRIDE_F 4.0f                 // 608 / 152
#define TPB      256
#define POS_PER_BLOCK 512             // 2 positions per thread

__device__ __forceinline__ float fast_sigmoid(float v) {
    return 1.0f / (1.0f + __expf(-v));
}

struct Vals { float v[NCH]; int gx, gy, a; };

__device__ __forceinline__ void load_pos(const float* __restrict__ x, int idx, Vals& r)
{
    const int s  = idx % GG;
    const int ba = idx / GG;
    r.a  = ba % NA;
    r.gx = s % GRID_G;
    r.gy = s / GRID_G;
    const float* __restrict__ p = x + (size_t)ba * (NCH * GG) + s;
#pragma unroll
    for (int c = 0; c < NCH; c++)
        r.v[c] = __ldcs(p + c * GG);
}

__device__ __forceinline__ void store_row(float* __restrict__ row, const Vals& r)
{
    const float aw = (r.a == 0) ? 11.0f : (r.a == 1) ? 24.0f : 42.0f;
    const float ah = (r.a == 0) ? 14.0f : (r.a == 1) ? 17.0f : 27.0f;
    row[0] = (fast_sigmoid(r.v[0]) + (float)r.gx) * STRIDE_F;
    row[1] = (fast_sigmoid(r.v[1]) + (float)r.gy) * STRIDE_F;
    row[2] = __expf(r.v[2]) * aw;
    row[3] = __expf(r.v[3]) * ah;
    row[4] = r.v[4];
    row[5] = r.v[5];
    row[6] = fast_sigmoid(r.v[6]);
    row[7] = fast_sigmoid(r.v[7]);
    row[8] = fast_sigmoid(r.v[8]);
    row[9] = fast_sigmoid(r.v[9]);
}

__global__ void __launch_bounds__(TPB)
yolo_layer_kernel(const float* __restrict__ x, float* __restrict__ out)
{
    __shared__ float sb[POS_PER_BLOCK * NCH];   // 20480 B staging

    const int t     = threadIdx.x;
    const int base  = blockIdx.x * POS_PER_BLOCK;
    const int idx0  = base + t;          // position 0
    const int idx1  = base + t + TPB;    // position 1

    // Issue both positions' loads up front (MLP = 20 per thread)
    Vals r0, r1;
    load_pos(x, idx0, r0);
    load_pos(x, idx1, r1);

    store_row(sb + t * NCH,         r0);
    store_row(sb + (t + TPB) * NCH, r1);

    __syncthreads();

    // Coalesced streaming copy: 5120 floats = 1280 float4 = 5 per thread.
    const float4* __restrict__ s4 = (const float4*)sb;
    float4* __restrict__ o4 = (float4*)(out + (size_t)base * NCH);
#pragma unroll
    for (int i = 0; i < 5; i++)
        __stcs(&o4[t + i * TPB], s4[t + i * TPB]);
}

extern "C" void kernel_launch(void* const* d_in, const int* in_sizes, int n_in,
                              void* d_out, int out_size)
{
    const float* x = (const float*)d_in[0];
    float* out = (float*)d_out;

    const int blocks = NPOS / POS_PER_BLOCK;   // 8664
    yolo_layer_kernel<<<blocks, TPB>>>(x, out);
}